// round 7
// baseline (speedup 1.0000x reference)
#include <cuda_runtime.h>

#define HID  128
#define NIN  64
#define NOUT 64
#define NB   256
#define NS   4096

typedef unsigned long long u64;

// xp[b][s][jp] = {xp[2jp], xp[2jp+1]} : x@Wx + bh + bx, j-pair packed. 512 MB.
__device__ u64 g_xp[NB][NS][HID / 2];
// hs[b][s][jp] = {h[2jp], h[2jp+1]}. 512 MB.
__device__ u64 g_hs[NB][NS][HID / 2];
// chunk carry
__device__ u64 g_h[NB][HID / 2];

__device__ __forceinline__ u64 ffma2(u64 a, u64 b, u64 c) {
    u64 d;
    asm("fma.rn.f32x2 %0, %1, %2, %3;" : "=l"(d) : "l"(a), "l"(b), "l"(c));
    return d;
}
__device__ __forceinline__ u64 fadd2(u64 a, u64 b) {
    u64 d;
    asm("add.rn.f32x2 %0, %1, %2;" : "=l"(d) : "l"(a), "l"(b));
    return d;
}
__device__ __forceinline__ u64 pack2(float x, float y) {
    u64 d;
    asm("mov.b64 %0, {%1, %2};" : "=l"(d) : "f"(x), "f"(y));
    return d;
}
__device__ __forceinline__ float2 unpack2(u64 v) {
    float2 r;
    asm("mov.b64 {%0, %1}, %2;" : "=f"(r.x), "=f"(r.y) : "l"(v));
    return r;
}
__device__ __forceinline__ u64 shfl_xor64(u64 v, int m) {
    return __shfl_xor_sync(0xffffffffu, v, m);
}
// skewed hbuf index: 2 u64 pad per 32-u64 block -> kq slices hit distinct banks
#define HB(k) ((k) + (((k) >> 5) << 1))

// ---------------------------------------------------------------------------
// Kernel 1 (v3): xp[b][s][jp] = x[b][s]@Wx + bh + bx  (j-pair packed u64)
// Grid (NS/32, NB), 256 threads, >=3 CTAs/SM. Thread t: jp = t>>2, iq = t&3.
// x tile duplicated {x,x} u64, quarter-strided rows: i at (i&15) + 18*(i>>4)
// -> the 4 iq base addresses land on banks 0/4/8/12 (conflict-free broadcast).
// iq partials reduced with shfl_xor(1,2); iq==0 lanes STG directly (coalesced
// 64B/warp per s).
// ---------------------------------------------------------------------------
__global__ void __launch_bounds__(256, 3) xp_kernel(
    const float* __restrict__ x,  const float* __restrict__ Wx,
    const float* __restrict__ bh, const float* __restrict__ bx)
{
    __shared__ __align__(16) u64 xt[32][72];    // duplicated {x,x}, quarter-strided

    const int t  = threadIdx.x;
    const int jp = t >> 2;
    const int iq = t & 3;
    const int j0 = 2 * jp;
    const int b  = blockIdx.y;
    const int s0 = blockIdx.x * 32;

    u64 wxp[16];
#pragma unroll
    for (int m = 0; m < 16; m++) {
        int i = iq * 16 + m;
        wxp[m] = *(const u64*)(Wx + i * HID + j0);   // {Wx[i][j0], Wx[i][j0+1]}
    }
    const u64 bias2 = pack2(bh[j0] + bx[j0], bh[j0 + 1] + bx[j0 + 1]);

    // Cooperative duplicated x tile load: 32 s x 64 i, 8 elems/thread.
#pragma unroll
    for (int q = 0; q < 8; q++) {
        int idx = t + q * 256;
        int s = idx >> 6, i = idx & 63;
        float v = x[((long long)b * NS + s0 + s) * NIN + i];
        xt[s][(i & 15) + 18 * (i >> 4)] = pack2(v, v);
    }
    __syncthreads();

#pragma unroll 4
    for (int s = 0; s < 32; s++) {
        const u64* xrow = &xt[s][iq * 18];
        u64 accA = 0, accB = 0;
#pragma unroll
        for (int m = 0; m < 16; m += 2) {
            ulonglong2 xv = *(const ulonglong2*)(xrow + m);
            accA = ffma2(wxp[m],     xv.x, accA);
            accB = ffma2(wxp[m + 1], xv.y, accB);
        }
        u64 acc = fadd2(accA, accB);
        acc = fadd2(acc, shfl_xor64(acc, 1));
        acc = fadd2(acc, shfl_xor64(acc, 2));
        if (iq == 0)
            g_xp[b][s0 + s][jp] = fadd2(acc, bias2);
    }
}

// ---------------------------------------------------------------------------
// Kernel 2: recurrence chunk [s0,s1), s0/s1 % 4 == 0.  (unchanged from R6)
// ---------------------------------------------------------------------------
__global__ void __launch_bounds__(512, 1) rnn_rec_chunk(
    const float* __restrict__ Wh, int s0, int s1)
{
    __shared__ __align__(16) u64 hbuf[2][2][134];       // [grp][buf][skewed 128]
    __shared__ __align__(16) u64 xpring[2][2][4][64];   // [grp][slot][st][jp]

    const int tid = threadIdx.x;
    const int gid = tid >> 8;
    const int t   = tid & 255;
    const int jp  = t >> 2;
    const int kq  = t & 3;
    const int j0  = 2 * jp;
    const int b   = blockIdx.x * 2 + gid;
    const int bar = gid + 1;

    // Wh pair slice: 32 x u64 = 64 regs.
    u64 whd[32];
#pragma unroll
    for (int m = 0; m < 32; m++) {
        int k = kq * 32 + m;
        whd[m] = *(const u64*)(Wh + k * HID + j0);
    }

    const int st_ld = t >> 6;
    const int jp_ld = t & 63;
    const int B0 = s0 >> 2, B1 = s1 >> 2;

    if (kq == 0) {
        float2 h0 = make_float2(0.f, 0.f);
        if (s0 != 0) h0 = unpack2(g_h[b][jp]);
        ulonglong2 w2;
        w2.x = pack2(h0.x, h0.x);
        w2.y = pack2(h0.y, h0.y);
        *(ulonglong2*)&hbuf[gid][0][HB(j0)] = w2;
    }
    xpring[gid][B0 & 1][st_ld][jp_ld] = g_xp[b][4 * B0 + st_ld][jp_ld];
    u64 xr = 0;
    if (4 * (B0 + 1) < NS) xr = g_xp[b][4 * (B0 + 1) + st_ld][jp_ld];
    asm volatile("bar.sync %0, 256;" :: "r"(bar) : "memory");

    for (int bc = B0; bc < B1; bc++) {
        xpring[gid][(bc + 1) & 1][st_ld][jp_ld] = xr;
        if (4 * (bc + 2) < NS) xr = g_xp[b][4 * (bc + 2) + st_ld][jp_ld];

#pragma unroll
        for (int st = 0; st < 4; st++) {
            const int cur = st & 1, nxt = cur ^ 1;

            u64 accA = 0;
            if (kq == 0) accA = xpring[gid][bc & 1][st][jp];
            u64 accB = 0;
            const u64* hb = &hbuf[gid][cur][kq * 34];
#pragma unroll
            for (int m = 0; m < 32; m += 2) {
                ulonglong2 hv = *(const ulonglong2*)(hb + m);
                accA = ffma2(whd[m],     hv.x, accA);
                accB = ffma2(whd[m + 1], hv.y, accB);
            }
            u64 acc = fadd2(accA, accB);
            acc = fadd2(acc, shfl_xor64(acc, 1));
            acc = fadd2(acc, shfl_xor64(acc, 2));

            if (kq == 0) {
                float2 tv = unpack2(acc);
                tv.x = fmaxf(tv.x, 0.f);
                tv.y = fmaxf(tv.y, 0.f);
                ulonglong2 w2;
                w2.x = pack2(tv.x, tv.x);
                w2.y = pack2(tv.y, tv.y);
                *(ulonglong2*)&hbuf[gid][nxt][HB(j0)] = w2;   // dup for next step
                u64 h2 = pack2(tv.x, tv.y);
                g_hs[b][4 * bc + st][jp] = h2;                // direct compact STG
                if (st == 3 && bc == B1 - 1) g_h[b][jp] = h2; // chunk carry
            }
            asm volatile("bar.sync %0, 256;" :: "r"(bar) : "memory");
        }
    }
}

// ---------------------------------------------------------------------------
// Kernel 3 (v2): out[b][s][o] = hs[b][s]@Wy + by.
// Grid (NS/32, NB), 256 threads, >=3 CTAs/SM. Thread (o = t>>2, jq = t&3),
// quarter-strided hs tile (banks 0/4/8/12 broadcast), cooperative STG.
// ---------------------------------------------------------------------------
__global__ void __launch_bounds__(256, 3) rnn_output(
    const float* __restrict__ Wy, const float* __restrict__ by,
    float* __restrict__ out)
{
    __shared__ __align__(16) u64   hst[32][72];
    __shared__ __align__(16) float ot[32][64];

    const int t  = threadIdx.x;
    const int o  = t >> 2;
    const int jq = t & 3;
    const int b  = blockIdx.y;
    const int s0 = blockIdx.x * 32;

    u64 wyp[16];
#pragma unroll
    for (int m = 0; m < 16; m++) {
        int jpp = jq * 16 + m;
        wyp[m] = pack2(Wy[(2 * jpp) * NOUT + o], Wy[(2 * jpp + 1) * NOUT + o]);
    }
    float byv = by[o];

    // Cooperative hs tile load: 32 s x 64 jp, 8 u64/thread.
#pragma unroll
    for (int q = 0; q < 8; q++) {
        int idx = t + q * 256;
        int s = idx >> 6, jj = idx & 63;
        hst[s][(jj & 15) + 18 * (jj >> 4)] = g_hs[b][s0 + s][jj];
    }
    __syncthreads();

#pragma unroll 4
    for (int s = 0; s < 32; s++) {
        const u64* hrow = &hst[s][jq * 18];
        u64 accA = 0, accB = 0;
#pragma unroll
        for (int m = 0; m < 16; m += 2) {
            ulonglong2 hv = *(const ulonglong2*)(hrow + m);
            accA = ffma2(wyp[m],     hv.x, accA);
            accB = ffma2(wyp[m + 1], hv.y, accB);
        }
        u64 acc = fadd2(accA, accB);
        acc = fadd2(acc, shfl_xor64(acc, 1));
        acc = fadd2(acc, shfl_xor64(acc, 2));
        if (jq == 0) {
            float2 a = unpack2(acc);
            ot[s][o] = a.x + a.y + byv;
        }
    }
    __syncthreads();

    // Cooperative coalesced output store: 32 s x 64 o floats, 8/thread.
#pragma unroll
    for (int q = 0; q < 8; q++) {
        int idx = t + q * 256;
        int s = idx >> 6, oo = idx & 63;
        out[((long long)b * NS + s0 + s) * NOUT + oo] = ot[s][oo];
    }
}

extern "C" void kernel_launch(void* const* d_in, const int* in_sizes, int n_in,
                              void* d_out, int out_size)
{
    const float* x  = (const float*)d_in[0];
    const float* Wh = (const float*)d_in[1];
    const float* bh = (const float*)d_in[2];
    const float* Wx = (const float*)d_in[3];
    const float* bx = (const float*)d_in[4];
    const float* Wy = (const float*)d_in[5];
    const float* by = (const float*)d_in[6];
    float* out = (float*)d_out;

    xp_kernel<<<dim3(NS / 32, NB), 256>>>(x, Wx, bh, bx);
    rnn_rec_chunk<<<NB / 2, 512>>>(Wh,    0, 1364);
    rnn_rec_chunk<<<NB / 2, 512>>>(Wh, 1364, 2732);
    rnn_rec_chunk<<<NB / 2, 512>>>(Wh, 2732, 4096);
    rnn_output<<<dim3(NS / 32, NB), 256>>>(Wy, by, out);
}

// round 8
// speedup vs baseline: 1.5831x; 1.5831x over previous
#include <cuda_runtime.h>

#define HID  128
#define NIN  64
#define NOUT 64
#define NB   256
#define NS   4096

typedef unsigned long long u64;

// hs[b][s][jp] = {h[2jp], h[2jp+1]}. 512 MB.
__device__ u64 g_hs[NB][NS][HID / 2];
// chunk carry
__device__ u64 g_h[NB][HID / 2];

__device__ __forceinline__ u64 ffma2(u64 a, u64 b, u64 c) {
    u64 d;
    asm("fma.rn.f32x2 %0, %1, %2, %3;" : "=l"(d) : "l"(a), "l"(b), "l"(c));
    return d;
}
__device__ __forceinline__ u64 fadd2(u64 a, u64 b) {
    u64 d;
    asm("add.rn.f32x2 %0, %1, %2;" : "=l"(d) : "l"(a), "l"(b));
    return d;
}
__device__ __forceinline__ u64 pack2(float x, float y) {
    u64 d;
    asm("mov.b64 %0, {%1, %2};" : "=l"(d) : "f"(x), "f"(y));
    return d;
}
__device__ __forceinline__ float2 unpack2(u64 v) {
    float2 r;
    asm("mov.b64 {%0, %1}, %2;" : "=f"(r.x), "=f"(r.y) : "l"(v));
    return r;
}
__device__ __forceinline__ u64 shfl_xor64(u64 v, int m) {
    return __shfl_xor_sync(0xffffffffu, v, m);
}
// skew: 2-u64 pad per 32-u64 block (keeps kh halves on distinct banks)
#define KSK(k) ((k) + (((k) >> 5) << 1))

// ---------------------------------------------------------------------------
// Recurrence chunk [s0,s1), s0/s1 % 4 == 0. Fused x-projection.
// Grid: 128 CTAs x 256 thr (1/SM, 256-reg budget). Two independent 128-thread
// row-groups per CTA (named barriers, 4 warps each).
// Thread (g = tid>>7, u = tid&127): jp = u>>1 (j-pair), kh = u&1 (k-half).
// whd[64] (128 regs) + wxd[32] (64 regs) register-resident.
// Per step: 48 LDS.128 + 96 FFMA2, ONE shfl_xor(1) reduction (intra-warp),
// one 128-thread named barrier. x streamed gmem->smem ring (4-step slack);
// h written dup to smem for next step + compact to g_hs.
// ---------------------------------------------------------------------------
__global__ void __launch_bounds__(256, 1) rnn_rec_chunk(
    const float* __restrict__ x,  const float* __restrict__ Wh,
    const float* __restrict__ bh, const float* __restrict__ Wx,
    const float* __restrict__ bx, int s0, int s1)
{
    __shared__ __align__(16) u64 hbuf[2][2][134];   // [grp][buf][dup-h, skewed]
    __shared__ __align__(16) u64 xs[2][2][4][66];   // [grp][slot][st][dup-x, skewed]

    const int tid = threadIdx.x;
    const int g   = tid >> 7;
    const int u   = tid & 127;
    const int jp  = u >> 1;       // 0..63
    const int kh  = u & 1;        // k-half (lane bit 0 -> shfl_xor(1) reduce)
    const int j0  = 2 * jp;
    const int b   = blockIdx.x * 2 + g;
    const int bar = g + 1;

    // Register-resident weight pair slices.
    u64 whd[64];
#pragma unroll
    for (int m = 0; m < 64; m++)
        whd[m] = *(const u64*)(Wh + (kh * 64 + m) * HID + j0);
    u64 wxd[32];
#pragma unroll
    for (int m = 0; m < 32; m++)
        wxd[m] = *(const u64*)(Wx + (kh * 32 + m) * HID + j0);
    u64 bias2 = 0;
    if (kh == 0)
        bias2 = pack2(bh[j0] + bx[j0], bh[j0 + 1] + bx[j0 + 1]);

    // x stager mapping: warp-uniform step stq, 32 lanes cover 64 i as float2.
    const int stq = u >> 5;            // step-in-block
    const int i2  = (u & 31) * 2;      // input col pair
    const float* xrow = x + (long long)b * NS * NIN;

    const int B0 = s0 >> 2, B1 = s1 >> 2;

    // Prologue: init h, stage x block B0, prefetch block B0+1.
    if (kh == 0) {
        float2 h0 = make_float2(0.f, 0.f);
        if (s0 != 0) h0 = unpack2(g_h[b][jp]);
        ulonglong2 w2;
        w2.x = pack2(h0.x, h0.x);
        w2.y = pack2(h0.y, h0.y);
        *(ulonglong2*)&hbuf[g][0][KSK(j0)] = w2;
    }
    {
        float2 v = *(const float2*)(xrow + (long long)(4 * B0 + stq) * NIN + i2);
        ulonglong2 w2;
        w2.x = pack2(v.x, v.x);
        w2.y = pack2(v.y, v.y);
        *(ulonglong2*)&xs[g][B0 & 1][stq][KSK(i2)] = w2;
    }
    float2 xr = make_float2(0.f, 0.f);
    if (4 * (B0 + 1) < NS)
        xr = *(const float2*)(xrow + (long long)(4 * (B0 + 1) + stq) * NIN + i2);
    asm volatile("bar.sync %0, 128;" :: "r"(bar) : "memory");

    for (int bc = B0; bc < B1; bc++) {
        // Block head: stage x block bc+1 (slot freed at end of block bc-1),
        // prefetch block bc+2 into regs.
        if (4 * (bc + 1) < NS) {
            ulonglong2 w2;
            w2.x = pack2(xr.x, xr.x);
            w2.y = pack2(xr.y, xr.y);
            *(ulonglong2*)&xs[g][(bc + 1) & 1][stq][KSK(i2)] = w2;
        }
        if (4 * (bc + 2) < NS)
            xr = *(const float2*)(xrow + (long long)(4 * (bc + 2) + stq) * NIN + i2);

#pragma unroll
        for (int st = 0; st < 4; st++) {
            const int cur = st & 1, nxt = cur ^ 1;   // 4*bc even -> s&1 == st&1

            u64 accA = bias2, accB = 0;              // bias2==0 for kh==1
            const u64* hb = &hbuf[g][cur][kh * 68];
#pragma unroll
            for (int m = 0; m < 32; m += 2) {
                ulonglong2 hv = *(const ulonglong2*)(hb + m);
                accA = ffma2(whd[m],     hv.x, accA);
                accB = ffma2(whd[m + 1], hv.y, accB);
            }
#pragma unroll
            for (int m = 32; m < 64; m += 2) {
                ulonglong2 hv = *(const ulonglong2*)(hb + m + 2);   // skip pad
                accA = ffma2(whd[m],     hv.x, accA);
                accB = ffma2(whd[m + 1], hv.y, accB);
            }
            const u64* xb = &xs[g][bc & 1][st][kh * 34];
#pragma unroll
            for (int m = 0; m < 32; m += 2) {
                ulonglong2 xv = *(const ulonglong2*)(xb + m);
                accA = ffma2(wxd[m],     xv.x, accA);
                accB = ffma2(wxd[m + 1], xv.y, accB);
            }
            u64 acc = fadd2(accA, accB);
            acc = fadd2(acc, shfl_xor64(acc, 1));    // combine k-halves

            if (kh == 0) {
                float2 tv = unpack2(acc);
                tv.x = fmaxf(tv.x, 0.f);
                tv.y = fmaxf(tv.y, 0.f);
                ulonglong2 w2;
                w2.x = pack2(tv.x, tv.x);
                w2.y = pack2(tv.y, tv.y);
                *(ulonglong2*)&hbuf[g][nxt][KSK(j0)] = w2;   // dup for next step
                u64 h2 = pack2(tv.x, tv.y);
                g_hs[b][4 * bc + st][jp] = h2;               // compact STG
                if (st == 3 && bc == B1 - 1) g_h[b][jp] = h2;
            }
            asm volatile("bar.sync %0, 128;" :: "r"(bar) : "memory");
        }
    }
}

// ---------------------------------------------------------------------------
// Output: out[b][s][o] = hs[b][s]@Wy + by.  (R6 16-step version, known-good)
// ---------------------------------------------------------------------------
__global__ void __launch_bounds__(256) rnn_output(
    const float* __restrict__ Wy, const float* __restrict__ by,
    float* __restrict__ out)
{
    __shared__ __align__(16) u64   hst[16][72];   // skewed, max index 69
    __shared__ __align__(16) float ot[16][64];

    const int t  = threadIdx.x;
    const int o  = t >> 2;
    const int jq = t & 3;
    const int b  = blockIdx.y;
    const int s0 = blockIdx.x * 16;

    u64 wyp[16];
#pragma unroll
    for (int m = 0; m < 16; m++) {
        int jpp = jq * 16 + m;
        wyp[m] = pack2(Wy[(2 * jpp) * NOUT + o], Wy[(2 * jpp + 1) * NOUT + o]);
    }
    float byv = by[o];

#pragma unroll
    for (int q = 0; q < 4; q++) {
        int idx = t + q * 256;
        int s = idx >> 6, jj = idx & 63;
        hst[s][jj + ((jj >> 4) << 1)] = g_hs[b][s0 + s][jj];
    }
    __syncthreads();

#pragma unroll 4
    for (int s = 0; s < 16; s++) {
        const u64* hrow = &hst[s][jq * 18];
        u64 accA = 0, accB = 0;
#pragma unroll
        for (int m = 0; m < 16; m += 2) {
            ulonglong2 hv = *(const ulonglong2*)(hrow + m);
            accA = ffma2(wyp[m],     hv.x, accA);
            accB = ffma2(wyp[m + 1], hv.y, accB);
        }
        u64 acc = fadd2(accA, accB);
        acc = fadd2(acc, shfl_xor64(acc, 1));
        acc = fadd2(acc, shfl_xor64(acc, 2));
        if (jq == 0) {
            float2 a = unpack2(acc);
            ot[s][o] = a.x + a.y + byv;
        }
    }
    __syncthreads();

#pragma unroll
    for (int q = 0; q < 4; q++) {
        int idx = t + q * 256;
        int s = idx >> 6, oo = idx & 63;
        out[((long long)b * NS + s0 + s) * NOUT + oo] = ot[s][oo];
    }
}

extern "C" void kernel_launch(void* const* d_in, const int* in_sizes, int n_in,
                              void* d_out, int out_size)
{
    const float* x  = (const float*)d_in[0];
    const float* Wh = (const float*)d_in[1];
    const float* bh = (const float*)d_in[2];
    const float* Wx = (const float*)d_in[3];
    const float* bx = (const float*)d_in[4];
    const float* Wy = (const float*)d_in[5];
    const float* by = (const float*)d_in[6];
    float* out = (float*)d_out;

    rnn_rec_chunk<<<NB / 2, 256>>>(x, Wh, bh, Wx, bx,    0, 1364);
    rnn_rec_chunk<<<NB / 2, 256>>>(x, Wh, bh, Wx, bx, 1364, 2732);
    rnn_rec_chunk<<<NB / 2, 256>>>(x, Wh, bh, Wx, bx, 2732, 4096);
    rnn_output<<<dim3(NS / 16, NB), 256>>>(Wy, by, out);
}